// round 12
// baseline (speedup 1.0000x reference)
#include <cuda_runtime.h>
#include <cuda_fp16.h>
#include <cstdint>

#define PADK 136           // halfs per smem row (128 + 8 pad) -> conflict-free LDSM
#define FULLMASK 0xffffffffu
#define NCTA 296           // 2 CTAs/SM x 148 SMs -> fully resident wave-1

// Scratch: per-node transformed features, fp16.
// Y[n, 0:128] = x[n] @ W1a (src half),  Y[n,128:256] = x[n] @ W1b (dst half)
__device__ __half g_Y[(size_t)50000 * 256];
__device__ unsigned g_bar = 0;   // epoch barrier counter (never reset)

// ---------------------------------------------------------------------------
__device__ __forceinline__ unsigned sptr(const void* p) {
    return (unsigned)__cvta_generic_to_shared(p);
}
__device__ __forceinline__ void ldsm4(unsigned a, unsigned& r0, unsigned& r1,
                                      unsigned& r2, unsigned& r3) {
    asm volatile("ldmatrix.sync.aligned.m8n8.x4.shared.b16 {%0,%1,%2,%3}, [%4];\n"
                 : "=r"(r0), "=r"(r1), "=r"(r2), "=r"(r3) : "r"(a));
}
__device__ __forceinline__ void mma16816(float* c, unsigned a0, unsigned a1,
                                         unsigned a2, unsigned a3,
                                         unsigned b0, unsigned b1) {
    asm volatile(
        "mma.sync.aligned.m16n8k16.row.col.f32.f16.f16.f32 "
        "{%0,%1,%2,%3}, {%4,%5,%6,%7}, {%8,%9}, {%0,%1,%2,%3};\n"
        : "+f"(c[0]), "+f"(c[1]), "+f"(c[2]), "+f"(c[3])
        : "r"(a0), "r"(a1), "r"(a2), "r"(a3), "r"(b0), "r"(b1));
}

// ---------------------------------------------------------------------------
// Warp-level 32x64x128 GEMM.
// ---------------------------------------------------------------------------
__device__ __forceinline__ void warp_mma_32x64(const __half* Aw, const __half* Bw,
                                               float acc[2][8][4], int lane) {
    unsigned a_addr = sptr(Aw + (size_t)(lane & 15) * PADK + ((lane & 16) ? 8 : 0));
    unsigned b_addr = sptr(Bw + (size_t)((lane & 7) + ((lane & 16) ? 8 : 0)) * PADK
                              + ((lane & 8) ? 8 : 0));
    #pragma unroll
    for (int k0 = 0; k0 < 128; k0 += 16) {
        unsigned a0[4], a1[4];
        ldsm4(a_addr + k0 * 2, a0[0], a0[1], a0[2], a0[3]);
        ldsm4(a_addr + 16 * PADK * 2 + k0 * 2, a1[0], a1[1], a1[2], a1[3]);
        #pragma unroll
        for (int np = 0; np < 4; np++) {
            unsigned b0, b1, b2, b3;
            ldsm4(b_addr + (unsigned)(np * 16 * PADK * 2) + k0 * 2, b0, b1, b2, b3);
            mma16816(acc[0][2 * np],     a0[0], a0[1], a0[2], a0[3], b0, b1);
            mma16816(acc[0][2 * np + 1], a0[0], a0[1], a0[2], a0[3], b2, b3);
            mma16816(acc[1][2 * np],     a1[0], a1[1], a1[2], a1[3], b0, b1);
            mma16816(acc[1][2 * np + 1], a1[0], a1[1], a1[2], a1[3], b2, b3);
        }
    }
}

// ---------------------------------------------------------------------------
// Fused kernel (grid NCTA, block 256, 2 CTAs/SM):
//   phase 1: Y[:, half*128:+128] = x @ W1-half   (R9-proven node shape)
//   (stage W2 + prefetch indices during barrier slack)
//   global epoch barrier (all NCTA CTAs are wave-1 resident)
//   phase 2: h = relu(Y[src,:128]+Y[dst,128:]+b1); out = h @ W2 + b2
// ---------------------------------------------------------------------------
__global__ __launch_bounds__(256, 2)
void fused_kernel(const float* __restrict__ x,
                  const void* __restrict__ edge_index,
                  const float* __restrict__ W1,
                  const float* __restrict__ b1,
                  const float* __restrict__ W2,
                  const float* __restrict__ b2,
                  float* __restrict__ out,
                  int n_nodes, int n_edges) {
    extern __shared__ __half smem[];
    __half* B0 = smem;                    // [128][PADK]
    __half* B1 = smem + 128 * PADK;       // [128][PADK]
    __half* BW = smem + 2 * 128 * PADK;   // weights (W1-half, then W2)
    __shared__ int s_is64;

    const int tid = threadIdx.x;
    const int warp = tid >> 5, lane = tid & 31;
    const int wm = warp & 3, wn = warp >> 2;   // 4M x 2N
    const int g = lane >> 2, t = lane & 3;

    // Per-CTA edge_index dtype detect (int64 LE small values => odd words 0)
    if (tid < 32) {
        const unsigned* w = (const unsigned*)edge_index;
        unsigned v = w[2 * tid + 1] | w[2 * (tid + 32) + 1];
        int any_nz = __any_sync(FULLMASK, v != 0u);
        if (tid == 0) s_is64 = any_nz ? 0 : 1;
    }

    // ================= phase 1: node GEMM =================
    const int half_sel = (blockIdx.x >= NCTA / 2) ? 1 : 0;
    const int xcta = blockIdx.x - half_sel * (NCTA / 2);

    // Stage this half of W1: BW[n][k] = W1[(k + 128*half)*128 + n]
    for (int i = tid; i < 128 * 128; i += 256) {
        int k = i >> 7, n = i & 127;
        BW[(size_t)n * PADK + k] =
            __float2half(W1[(size_t)(k + (half_sel << 7)) * 128 + n]);
    }

    const int node_tiles = (n_nodes + 127) >> 7;
    int li = 0;
    for (int tile = xcta; tile < node_tiles; tile += NCTA / 2, li++) {
        __half* As = (li & 1) ? B1 : B0;
        const int row0 = tile << 7;

        for (int i = tid; i < 128 * 32; i += 256) {
            int r = i >> 5, c4 = i & 31;
            int gr = row0 + r;
            float4 v = make_float4(0.f, 0.f, 0.f, 0.f);
            if (gr < n_nodes) v = ((const float4*)x)[(size_t)gr * 32 + c4];
            __half* dst = As + (size_t)r * PADK + c4 * 4;
            dst[0] = __float2half(v.x); dst[1] = __float2half(v.y);
            dst[2] = __float2half(v.z); dst[3] = __float2half(v.w);
        }
        __syncthreads();   // A ready (also staged BW on first iter)

        float acc[2][8][4];
        #pragma unroll
        for (int mi = 0; mi < 2; mi++)
            #pragma unroll
            for (int n8 = 0; n8 < 8; n8++)
                acc[mi][n8][0] = acc[mi][n8][1] = acc[mi][n8][2] = acc[mi][n8][3] = 0.f;

        warp_mma_32x64(As + (size_t)(wm * 32) * PADK,
                       BW + (size_t)(wn * 64) * PADK, acc, lane);

        __half* Yb = g_Y + (half_sel << 7);
        #pragma unroll
        for (int mi = 0; mi < 2; mi++) {
            const int r0 = row0 + wm * 32 + mi * 16 + g;
            #pragma unroll
            for (int n8 = 0; n8 < 8; n8++) {
                int col = wn * 64 + n8 * 8 + 2 * t;
                if (r0 < n_nodes)
                    *(__half2*)(Yb + (size_t)r0 * 256 + col) =
                        __floats2half2_rn(acc[mi][n8][0], acc[mi][n8][1]);
                if (r0 + 8 < n_nodes)
                    *(__half2*)(Yb + (size_t)(r0 + 8) * 256 + col) =
                        __floats2half2_rn(acc[mi][n8][2], acc[mi][n8][3]);
            }
        }
        // ping-pong A: no second sync needed (proven R9)
    }
    __syncthreads();   // all phase-1 smem reads complete; s_is64 visible

    // ===== overlap with barrier slack: stage W2, prefetch indices =====
    for (int i = tid; i < 128 * 128; i += 256) {
        int k = i >> 7, n = i & 127;
        BW[(size_t)n * PADK + k] = __float2half(W2[i]);  // W2[k*128+n]
    }

    const int is64 = s_is64;
    const long long* idx64 = (const long long*)edge_index;
    const int*       idx32 = (const int*)edge_index;
    const int edge_tiles = (n_edges + 127) >> 7;

    auto load_idx = [&](int tl) -> int {
        int myE = (tl << 7) + (warp << 4) + (lane & 15);
        if (myE >= n_edges) myE = n_edges - 1;
        size_t off = (lane < 16) ? (size_t)myE : (size_t)n_edges + (size_t)myE;
        return is64 ? (int)idx64[off] : idx32[off];
    };

    int tile = blockIdx.x;
    int vidx = (tile < edge_tiles) ? load_idx(tile) : 0;

    // ================= global epoch barrier =================
    __syncthreads();
    if (tid == 0) {
        __threadfence();                       // release Y writes (cumulative)
        unsigned tk = atomicAdd(&g_bar, 1);
        unsigned target = (tk / NCTA + 1) * NCTA;
        while (atomicAdd(&g_bar, 0u) < target) __nanosleep(64);
        __threadfence();                       // acquire
    }
    __syncthreads();   // releases CTA; W2 STS also ordered

    // ================= phase 2: edge loop =================
    const float4 b1v = *(const float4*)(b1 + lane * 4);
    const __half2 b1h0 = __floats2half2_rn(b1v.x, b1v.y);
    const __half2 b1h1 = __floats2half2_rn(b1v.z, b1v.w);
    const __half2 hzero = __float2half2_rn(0.f);
    const bool oddt = (t & 1);

    float2 breg[8];
    #pragma unroll
    for (int n8 = 0; n8 < 8; n8++)
        breg[n8] = *(const float2*)(b2 + wn * 64 + n8 * 8 + 2 * t);
    int colq[4];
    #pragma unroll
    for (int q = 0; q < 4; q++)
        colq[q] = wn * 64 + 16 * q + (oddt ? 8 + 2 * (t - 1) : 2 * t);

    if (tile >= edge_tiles) return;

    int lj = 0;
    while (true) {
        __half* Hs = (lj & 1) ? B1 : B0;
        const int e0 = tile << 7;

        // ---- warp-cooperative gather, batch x8, half2 math ----
        {
            __half* Hrow = Hs + (size_t)(warp << 4) * PADK + lane * 4;
            #pragma unroll
            for (int i = 0; i < 16; i += 8) {
                uint2 va[8], vd[8];
                #pragma unroll
                for (int j = 0; j < 8; j++) {
                    int s = __shfl_sync(FULLMASK, vidx, i + j);
                    int d = __shfl_sync(FULLMASK, vidx, 16 + i + j);
                    va[j] = *(const uint2*)(g_Y + (size_t)s * 256 + lane * 4);
                    vd[j] = *(const uint2*)(g_Y + (size_t)d * 256 + 128 + lane * 4);
                }
                #pragma unroll
                for (int j = 0; j < 8; j++) {
                    __half2 s0 = *(const __half2*)&va[j].x;
                    __half2 s1 = *(const __half2*)&va[j].y;
                    __half2 d0 = *(const __half2*)&vd[j].x;
                    __half2 d1 = *(const __half2*)&vd[j].y;
                    __half2 r0 = __hmax2(__hadd2(__hadd2(s0, d0), b1h0), hzero);
                    __half2 r1 = __hmax2(__hadd2(__hadd2(s1, d1), b1h1), hzero);
                    uint2 rv;
                    rv.x = *(const unsigned*)&r0;
                    rv.y = *(const unsigned*)&r1;
                    *(uint2*)(Hrow + (size_t)(i + j) * PADK) = rv;
                }
            }
        }
        __syncthreads();   // H ready; all warps past previous tile's MMA

        // ---- prefetch next tile's indices (hidden under MMA) ----
        const int next = tile + NCTA;
        const bool more = next < edge_tiles;
        int vnext = more ? load_idx(next) : 0;

        // ---- 32x64 warp-tile GEMM; acc pre-seeded with b2 ----
        float acc[2][8][4];
        #pragma unroll
        for (int mi = 0; mi < 2; mi++)
            #pragma unroll
            for (int n8 = 0; n8 < 8; n8++) {
                acc[mi][n8][0] = breg[n8].x; acc[mi][n8][1] = breg[n8].y;
                acc[mi][n8][2] = breg[n8].x; acc[mi][n8][3] = breg[n8].y;
            }

        warp_mma_32x64(Hs + (size_t)(wm * 32) * PADK,
                       BW + (size_t)(wn * 64) * PADK, acc, lane);

        // ---- epilogue: shfl-merge lane pairs -> float4, STG.128 ----
        #pragma unroll
        for (int mi = 0; mi < 2; mi++) {
            const int r0 = e0 + wm * 32 + mi * 16 + g;
            #pragma unroll
            for (int q = 0; q < 4; q++) {
                const int n8e = 2 * q, n8o = 2 * q + 1;
                float s0 = oddt ? acc[mi][n8e][0] : acc[mi][n8o][0];
                float s1 = oddt ? acc[mi][n8e][1] : acc[mi][n8o][1];
                float s2 = oddt ? acc[mi][n8e][2] : acc[mi][n8o][2];
                float s3 = oddt ? acc[mi][n8e][3] : acc[mi][n8o][3];
                float x0 = __shfl_xor_sync(FULLMASK, s0, 1);
                float x1 = __shfl_xor_sync(FULLMASK, s1, 1);
                float x2 = __shfl_xor_sync(FULLMASK, s2, 1);
                float x3 = __shfl_xor_sync(FULLMASK, s3, 1);
                float4 v0, v1;
                if (!oddt) {
                    v0 = make_float4(acc[mi][n8e][0], acc[mi][n8e][1], x0, x1);
                    v1 = make_float4(acc[mi][n8e][2], acc[mi][n8e][3], x2, x3);
                } else {
                    v0 = make_float4(x0, x1, acc[mi][n8o][0], acc[mi][n8o][1]);
                    v1 = make_float4(x2, x3, acc[mi][n8o][2], acc[mi][n8o][3]);
                }
                if (r0 < n_edges)
                    *(float4*)(out + (size_t)r0 * 128 + colq[q]) = v0;
                if (r0 + 8 < n_edges)
                    *(float4*)(out + (size_t)(r0 + 8) * 128 + colq[q]) = v1;
            }
        }

        if (!more) break;
        tile = next; vidx = vnext; lj++;
        // ping-pong H: next gather targets the other buffer
    }
}

// ---------------------------------------------------------------------------
extern "C" void kernel_launch(void* const* d_in, const int* in_sizes, int n_in,
                              void* d_out, int out_size) {
    const float* x  = (const float*)d_in[0];
    const void*  ei = d_in[1];
    const float* W1 = (const float*)d_in[2];
    const float* b1 = (const float*)d_in[3];
    const float* W2 = (const float*)d_in[4];
    const float* b2 = (const float*)d_in[5];
    float* out = (float*)d_out;

    const int n_nodes = in_sizes[0] / 128;
    const int n_edges = in_sizes[1] / 2;

    const int smem3 = 3 * 128 * PADK * (int)sizeof(__half);   // 104448
    static bool attr_set = false;
    if (!attr_set) {
        cudaFuncSetAttribute(fused_kernel,
                             cudaFuncAttributeMaxDynamicSharedMemorySize, smem3);
        attr_set = true;
    }

    fused_kernel<<<NCTA, 256, smem3>>>(x, ei, W1, b1, W2, b2, out,
                                       n_nodes, n_edges);
}

// round 13
// speedup vs baseline: 1.0227x; 1.0227x over previous
#include <cuda_runtime.h>
#include <cuda_fp16.h>
#include <cstdint>

#define PADK 136           // halfs per smem row (128 + 8 pad) -> conflict-free LDSM
#define FULLMASK 0xffffffffu

// Scratch: per-node transformed features, fp16.
// Y[n, 0:128] = x[n] @ W1a (src half),  Y[n,128:256] = x[n] @ W1b (dst half)
__device__ __half g_Y[(size_t)50000 * 256];
__device__ int g_idx64;

// ---------------------------------------------------------------------------
__device__ __forceinline__ unsigned sptr(const void* p) {
    return (unsigned)__cvta_generic_to_shared(p);
}
__device__ __forceinline__ void ldsm4(unsigned a, unsigned& r0, unsigned& r1,
                                      unsigned& r2, unsigned& r3) {
    asm volatile("ldmatrix.sync.aligned.m8n8.x4.shared.b16 {%0,%1,%2,%3}, [%4];\n"
                 : "=r"(r0), "=r"(r1), "=r"(r2), "=r"(r3) : "r"(a));
}
__device__ __forceinline__ void mma16816(float* c, unsigned a0, unsigned a1,
                                         unsigned a2, unsigned a3,
                                         unsigned b0, unsigned b1) {
    asm volatile(
        "mma.sync.aligned.m16n8k16.row.col.f32.f16.f16.f32 "
        "{%0,%1,%2,%3}, {%4,%5,%6,%7}, {%8,%9}, {%0,%1,%2,%3};\n"
        : "+f"(c[0]), "+f"(c[1]), "+f"(c[2]), "+f"(c[3])
        : "r"(a0), "r"(a1), "r"(a2), "r"(a3), "r"(b0), "r"(b1));
}

// ---------------------------------------------------------------------------
// Warp-level 32x64x128 GEMM.
// ---------------------------------------------------------------------------
__device__ __forceinline__ void warp_mma_32x64(const __half* Aw, const __half* Bw,
                                               float acc[2][8][4], int lane) {
    unsigned a_addr = sptr(Aw + (size_t)(lane & 15) * PADK + ((lane & 16) ? 8 : 0));
    unsigned b_addr = sptr(Bw + (size_t)((lane & 7) + ((lane & 16) ? 8 : 0)) * PADK
                              + ((lane & 8) ? 8 : 0));
    #pragma unroll
    for (int k0 = 0; k0 < 128; k0 += 16) {
        unsigned a0[4], a1[4];
        ldsm4(a_addr + k0 * 2, a0[0], a0[1], a0[2], a0[3]);
        ldsm4(a_addr + 16 * PADK * 2 + k0 * 2, a1[0], a1[1], a1[2], a1[3]);
        #pragma unroll
        for (int np = 0; np < 4; np++) {
            unsigned b0, b1, b2, b3;
            ldsm4(b_addr + (unsigned)(np * 16 * PADK * 2) + k0 * 2, b0, b1, b2, b3);
            mma16816(acc[0][2 * np],     a0[0], a0[1], a0[2], a0[3], b0, b1);
            mma16816(acc[0][2 * np + 1], a0[0], a0[1], a0[2], a0[3], b2, b3);
            mma16816(acc[1][2 * np],     a1[0], a1[1], a1[2], a1[3], b0, b1);
            mma16816(acc[1][2 * np + 1], a1[0], a1[1], a1[2], a1[3], b2, b3);
        }
    }
}

// ---------------------------------------------------------------------------
// Node kernel (persistent, block 256, 2 CTAs/SM via y-split) — R10 proven.
// ---------------------------------------------------------------------------
__global__ __launch_bounds__(256, 2)
void node_gemm_kernel(const float* __restrict__ x,
                      const float* __restrict__ W1,
                      const void* __restrict__ ei,
                      int n_nodes) {
    extern __shared__ __half smem[];
    __half* As0 = smem;                   // [128][PADK]
    __half* As1 = smem + 128 * PADK;
    __half* Ws  = smem + 2 * 128 * PADK;  // [128 cols][PADK k] for this half

    const int tid = threadIdx.x;
    const int half_sel = blockIdx.y;

    if (blockIdx.x == 0 && half_sel == 0 && tid < 32) {
        const unsigned* w = (const unsigned*)ei;
        unsigned v = w[2 * tid + 1] | w[2 * (tid + 32) + 1];
        int any_nz = __any_sync(FULLMASK, v != 0u);
        if (tid == 0) g_idx64 = any_nz ? 0 : 1;
    }

    for (int i = tid; i < 128 * 128; i += 256) {
        int k = i >> 7, n = i & 127;
        Ws[(size_t)n * PADK + k] =
            __float2half(W1[(size_t)(k + (half_sel << 7)) * 128 + n]);
    }

    const int warp = tid >> 5, lane = tid & 31;
    const int wm = warp & 3, wn = warp >> 2;   // 4M x 2N
    const int g = lane >> 2, t = lane & 3;
    const int n_tiles = (n_nodes + 127) >> 7;

    int li = 0;
    for (int tile = blockIdx.x; tile < n_tiles; tile += gridDim.x, li++) {
        __half* As = (li & 1) ? As1 : As0;
        const int row0 = tile << 7;

        for (int i = tid; i < 128 * 32; i += 256) {
            int r = i >> 5, c4 = i & 31;
            int gr = row0 + r;
            float4 v = make_float4(0.f, 0.f, 0.f, 0.f);
            if (gr < n_nodes) v = ((const float4*)x)[(size_t)gr * 32 + c4];
            __half* dst = As + (size_t)r * PADK + c4 * 4;
            dst[0] = __float2half(v.x); dst[1] = __float2half(v.y);
            dst[2] = __float2half(v.z); dst[3] = __float2half(v.w);
        }
        __syncthreads();

        float acc[2][8][4];
        #pragma unroll
        for (int mi = 0; mi < 2; mi++)
            #pragma unroll
            for (int n8 = 0; n8 < 8; n8++)
                acc[mi][n8][0] = acc[mi][n8][1] = acc[mi][n8][2] = acc[mi][n8][3] = 0.f;

        warp_mma_32x64(As + (size_t)(wm * 32) * PADK,
                       Ws + (size_t)(wn * 64) * PADK, acc, lane);

        __half* Yb = g_Y + (half_sel << 7);
        #pragma unroll
        for (int mi = 0; mi < 2; mi++) {
            const int r0 = row0 + wm * 32 + mi * 16 + g;
            #pragma unroll
            for (int n8 = 0; n8 < 8; n8++) {
                int col = wn * 64 + n8 * 8 + 2 * t;
                if (r0 < n_nodes)
                    *(__half2*)(Yb + (size_t)r0 * 256 + col) =
                        __floats2half2_rn(acc[mi][n8][0], acc[mi][n8][1]);
                if (r0 + 8 < n_nodes)
                    *(__half2*)(Yb + (size_t)(r0 + 8) * 256 + col) =
                        __floats2half2_rn(acc[mi][n8][2], acc[mi][n8][3]);
            }
        }
    }
}

// ---------------------------------------------------------------------------
// Edge kernel (persistent, block 256, 2 CTAs/SM) — R10 base, gather now
// 2 edges per LDG.128 (lanes 0-15: edge i, lanes 16-31: edge i+1):
// halves gather LDG and STS instruction counts at identical byte traffic.
// ---------------------------------------------------------------------------
__global__ __launch_bounds__(256, 2)
void edge_kernel(const void* __restrict__ edge_index,
                 const float* __restrict__ b1,
                 const float* __restrict__ W2,
                 const float* __restrict__ b2,
                 float* __restrict__ out,
                 int n_edges) {
    extern __shared__ __half smem[];
    __half* Hs0 = smem;                   // [128][PADK]
    __half* Hs1 = smem + 128 * PADK;
    __half* Ws  = smem + 2 * 128 * PADK;  // [128 n][PADK k] = W2[k][n]

    const int tid = threadIdx.x;
    const int warp = tid >> 5, lane = tid & 31;
    const int wm = warp & 3, wn = warp >> 2;   // 4M x 2N
    const int g = lane >> 2, t = lane & 3;
    const bool oddt = (t & 1);
    const int l16 = lane & 15;
    const int hsel = lane >> 4;                // 0: edge i, 1: edge i+1

    // Stage W2 once (transposed; coalesced on global side)
    for (int i = tid; i < 128 * 128; i += 256) {
        int k = i >> 7, n = i & 127;
        Ws[(size_t)n * PADK + k] = __float2half(W2[i]);  // W2[k*128+n]
    }

    // Per-lane constants: b1 chunk cols l16*8 .. +8 (4 half2)
    __half2 b1h[4];
    {
        float4 bA = __ldg((const float4*)(b1 + l16 * 8));
        float4 bB = __ldg((const float4*)(b1 + l16 * 8 + 4));
        b1h[0] = __floats2half2_rn(bA.x, bA.y);
        b1h[1] = __floats2half2_rn(bA.z, bA.w);
        b1h[2] = __floats2half2_rn(bB.x, bB.y);
        b1h[3] = __floats2half2_rn(bB.z, bB.w);
    }
    const __half2 hzero = __float2half2_rn(0.f);

    int colq[4];
    float4 b2v[4];
    #pragma unroll
    for (int q = 0; q < 4; q++) {
        colq[q] = wn * 64 + 16 * q + (oddt ? 8 + 2 * (t - 1) : 2 * t);
        b2v[q] = *(const float4*)(b2 + colq[q]);
    }

    const int is64 = g_idx64;
    const long long* idx64 = (const long long*)edge_index;
    const int*       idx32 = (const int*)edge_index;
    const int n_tiles = (n_edges + 127) >> 7;

    auto load_idx = [&](int tl) -> int {
        int myE = (tl << 7) + (warp << 4) + l16;
        if (myE >= n_edges) myE = n_edges - 1;
        size_t off = (lane < 16) ? (size_t)myE : (size_t)n_edges + (size_t)myE;
        return is64 ? (int)idx64[off] : idx32[off];
    };

    int tile = blockIdx.x;
    if (tile >= n_tiles) return;
    int vidx = load_idx(tile);   // prologue index load (covered by Ws staging)

    int li = 0;
    while (true) {
        __half* Hs = (li & 1) ? Hs1 : Hs0;
        const int e0 = tile << 7;

        // ---- gather: 2 edges per LDG.128, batched x4 pairs ----
        {
            // this lane stores edge row (pair base + hsel), 16B at col l16*8
            __half* Hlane = Hs + (size_t)((warp << 4) + hsel) * PADK + l16 * 8;
            #pragma unroll
            for (int i = 0; i < 16; i += 8) {     // two batches of 4 pairs
                uint4 va[4], vd[4];
                #pragma unroll
                for (int j = 0; j < 4; j++) {
                    int p0 = i + 2 * j;           // pair base edge
                    int sA = __shfl_sync(FULLMASK, vidx, p0);
                    int sB = __shfl_sync(FULLMASK, vidx, p0 + 1);
                    int dA = __shfl_sync(FULLMASK, vidx, 16 + p0);
                    int dB = __shfl_sync(FULLMASK, vidx, 16 + p0 + 1);
                    int s = hsel ? sB : sA;
                    int d = hsel ? dB : dA;
                    va[j] = *(const uint4*)(g_Y + (size_t)s * 256 + l16 * 8);
                    vd[j] = *(const uint4*)(g_Y + (size_t)d * 256 + 128 + l16 * 8);
                }
                #pragma unroll
                for (int j = 0; j < 4; j++) {
                    const __half2* hs = (const __half2*)&va[j];
                    const __half2* hd = (const __half2*)&vd[j];
                    __half2 r[4];
                    #pragma unroll
                    for (int q = 0; q < 4; q++)
                        r[q] = __hmax2(__hadd2(__hadd2(hs[q], hd[q]), b1h[q]),
                                       hzero);
                    *(uint4*)(Hlane + (size_t)(i + 2 * j) * PADK) =
                        *(const uint4*)r;
                }
            }
        }
        __syncthreads();   // H ready; all warps past previous tile's MMA

        // ---- prefetch next tile's indices (latency hidden under MMA) ----
        const int next = tile + gridDim.x;
        const bool more = next < n_tiles;
        int vnext = more ? load_idx(next) : 0;

        // ---- 32x64 warp-tile GEMM ----
        float acc[2][8][4];
        #pragma unroll
        for (int mi = 0; mi < 2; mi++)
            #pragma unroll
            for (int n8 = 0; n8 < 8; n8++)
                acc[mi][n8][0] = acc[mi][n8][1] = acc[mi][n8][2] = acc[mi][n8][3] = 0.f;

        warp_mma_32x64(Hs + (size_t)(wm * 32) * PADK,
                       Ws + (size_t)(wn * 64) * PADK, acc, lane);

        // ---- epilogue: shfl-merge lane pairs -> float4, +b2, STG.128 ----
        #pragma unroll
        for (int mi = 0; mi < 2; mi++) {
            const int r0 = e0 + wm * 32 + mi * 16 + g;
            #pragma unroll
            for (int q = 0; q < 4; q++) {
                const int n8e = 2 * q, n8o = 2 * q + 1;
                float s0 = oddt ? acc[mi][n8e][0] : acc[mi][n8o][0];
                float s1 = oddt ? acc[mi][n8e][1] : acc[mi][n8o][1];
                float s2 = oddt ? acc[mi][n8e][2] : acc[mi][n8o][2];
                float s3 = oddt ? acc[mi][n8e][3] : acc[mi][n8o][3];
                float x0 = __shfl_xor_sync(FULLMASK, s0, 1);
                float x1 = __shfl_xor_sync(FULLMASK, s1, 1);
                float x2 = __shfl_xor_sync(FULLMASK, s2, 1);
                float x3 = __shfl_xor_sync(FULLMASK, s3, 1);
                float4 v0, v1;
                if (!oddt) {
                    v0 = make_float4(acc[mi][n8e][0], acc[mi][n8e][1], x0, x1);
                    v1 = make_float4(acc[mi][n8e][2], acc[mi][n8e][3], x2, x3);
                } else {
                    v0 = make_float4(x0, x1, acc[mi][n8o][0], acc[mi][n8o][1]);
                    v1 = make_float4(x2, x3, acc[mi][n8o][2], acc[mi][n8o][3]);
                }
                v0.x += b2v[q].x; v0.y += b2v[q].y; v0.z += b2v[q].z; v0.w += b2v[q].w;
                v1.x += b2v[q].x; v1.y += b2v[q].y; v1.z += b2v[q].z; v1.w += b2v[q].w;
                if (r0 < n_edges)
                    *(float4*)(out + (size_t)r0 * 128 + colq[q]) = v0;
                if (r0 + 8 < n_edges)
                    *(float4*)(out + (size_t)(r0 + 8) * 128 + colq[q]) = v1;
            }
        }

        if (!more) break;
        tile = next; vidx = vnext; li++;
        // no extra sync: ping-pong H; next gather targets the other buffer
    }
}

// ---------------------------------------------------------------------------
extern "C" void kernel_launch(void* const* d_in, const int* in_sizes, int n_in,
                              void* d_out, int out_size) {
    const float* x  = (const float*)d_in[0];
    const void*  ei = d_in[1];
    const float* W1 = (const float*)d_in[2];
    const float* b1 = (const float*)d_in[3];
    const float* W2 = (const float*)d_in[4];
    const float* b2 = (const float*)d_in[5];
    float* out = (float*)d_out;

    const int n_nodes = in_sizes[0] / 128;
    const int n_edges = in_sizes[1] / 2;

    const int smem3 = 3 * 128 * PADK * (int)sizeof(__half);   // 104448
    static bool attr_set = false;
    if (!attr_set) {
        cudaFuncSetAttribute(node_gemm_kernel,
                             cudaFuncAttributeMaxDynamicSharedMemorySize, smem3);
        cudaFuncSetAttribute(edge_kernel,
                             cudaFuncAttributeMaxDynamicSharedMemorySize, smem3);
        attr_set = true;
    }

    const int node_tiles = (n_nodes + 127) / 128;
    int g1x = node_tiles < 148 ? node_tiles : 148;
    dim3 g1(g1x, 2);
    node_gemm_kernel<<<g1, 256, smem3>>>(x, W1, ei, n_nodes);

    const int edge_tiles = (n_edges + 127) / 128;
    int g2 = edge_tiles < 296 ? edge_tiles : 296;
    edge_kernel<<<g2, 256, smem3>>>(ei, b1, W2, b2, out, n_edges);
}

// round 14
// speedup vs baseline: 1.1601x; 1.1344x over previous
#include <cuda_runtime.h>
#include <cuda_fp16.h>
#include <cstdint>

#define PADK 136           // halfs per smem row (128 + 8 pad) -> conflict-free LDSM
#define FULLMASK 0xffffffffu

// Scratch: per-node transformed features, fp16.
// Y[n, 0:128] = x[n] @ W1a (src half),  Y[n,128:256] = x[n] @ W1b (dst half)
__device__ __half g_Y[(size_t)50000 * 256];
__device__ int g_idx64;

// ---------------------------------------------------------------------------
__device__ __forceinline__ unsigned sptr(const void* p) {
    return (unsigned)__cvta_generic_to_shared(p);
}
__device__ __forceinline__ void ldsm4(unsigned a, unsigned& r0, unsigned& r1,
                                      unsigned& r2, unsigned& r3) {
    asm volatile("ldmatrix.sync.aligned.m8n8.x4.shared.b16 {%0,%1,%2,%3}, [%4];\n"
                 : "=r"(r0), "=r"(r1), "=r"(r2), "=r"(r3) : "r"(a));
}
__device__ __forceinline__ void mma16816(float* c, unsigned a0, unsigned a1,
                                         unsigned a2, unsigned a3,
                                         unsigned b0, unsigned b1) {
    asm volatile(
        "mma.sync.aligned.m16n8k16.row.col.f32.f16.f16.f32 "
        "{%0,%1,%2,%3}, {%4,%5,%6,%7}, {%8,%9}, {%0,%1,%2,%3};\n"
        : "+f"(c[0]), "+f"(c[1]), "+f"(c[2]), "+f"(c[3])
        : "r"(a0), "r"(a1), "r"(a2), "r"(a3), "r"(b0), "r"(b1));
}
__device__ __forceinline__ void stg128_cs(float* p, float4 v) {
    asm volatile("st.global.cs.v4.f32 [%0], {%1,%2,%3,%4};\n"
                 :: "l"(p), "f"(v.x), "f"(v.y), "f"(v.z), "f"(v.w) : "memory");
}

// ---------------------------------------------------------------------------
// Warp-level 32x64x128 GEMM.
// ---------------------------------------------------------------------------
__device__ __forceinline__ void warp_mma_32x64(const __half* Aw, const __half* Bw,
                                               float acc[2][8][4], int lane) {
    unsigned a_addr = sptr(Aw + (size_t)(lane & 15) * PADK + ((lane & 16) ? 8 : 0));
    unsigned b_addr = sptr(Bw + (size_t)((lane & 7) + ((lane & 16) ? 8 : 0)) * PADK
                              + ((lane & 8) ? 8 : 0));
    #pragma unroll
    for (int k0 = 0; k0 < 128; k0 += 16) {
        unsigned a0[4], a1[4];
        ldsm4(a_addr + k0 * 2, a0[0], a0[1], a0[2], a0[3]);
        ldsm4(a_addr + 16 * PADK * 2 + k0 * 2, a1[0], a1[1], a1[2], a1[3]);
        #pragma unroll
        for (int np = 0; np < 4; np++) {
            unsigned b0, b1, b2, b3;
            ldsm4(b_addr + (unsigned)(np * 16 * PADK * 2) + k0 * 2, b0, b1, b2, b3);
            mma16816(acc[0][2 * np],     a0[0], a0[1], a0[2], a0[3], b0, b1);
            mma16816(acc[0][2 * np + 1], a0[0], a0[1], a0[2], a0[3], b2, b3);
            mma16816(acc[1][2 * np],     a1[0], a1[1], a1[2], a1[3], b0, b1);
            mma16816(acc[1][2 * np + 1], a1[0], a1[1], a1[2], a1[3], b2, b3);
        }
    }
}

// ---------------------------------------------------------------------------
// Node kernel (persistent, block 256, 2 CTAs/SM via y-split) — R10 proven.
// ---------------------------------------------------------------------------
__global__ __launch_bounds__(256, 2)
void node_gemm_kernel(const float* __restrict__ x,
                      const float* __restrict__ W1,
                      const void* __restrict__ ei,
                      int n_nodes) {
    extern __shared__ __half smem[];
    __half* As0 = smem;                   // [128][PADK]
    __half* As1 = smem + 128 * PADK;
    __half* Ws  = smem + 2 * 128 * PADK;  // [128 cols][PADK k] for this half

    const int tid = threadIdx.x;
    const int half_sel = blockIdx.y;

    if (blockIdx.x == 0 && half_sel == 0 && tid < 32) {
        const unsigned* w = (const unsigned*)ei;
        unsigned v = w[2 * tid + 1] | w[2 * (tid + 32) + 1];
        int any_nz = __any_sync(FULLMASK, v != 0u);
        if (tid == 0) g_idx64 = any_nz ? 0 : 1;
    }

    for (int i = tid; i < 128 * 128; i += 256) {
        int k = i >> 7, n = i & 127;
        Ws[(size_t)n * PADK + k] =
            __float2half(W1[(size_t)(k + (half_sel << 7)) * 128 + n]);
    }

    const int warp = tid >> 5, lane = tid & 31;
    const int wm = warp & 3, wn = warp >> 2;   // 4M x 2N
    const int g = lane >> 2, t = lane & 3;
    const int n_tiles = (n_nodes + 127) >> 7;

    int li = 0;
    for (int tile = blockIdx.x; tile < n_tiles; tile += gridDim.x, li++) {
        __half* As = (li & 1) ? As1 : As0;
        const int row0 = tile << 7;

        for (int i = tid; i < 128 * 32; i += 256) {
            int r = i >> 5, c4 = i & 31;
            int gr = row0 + r;
            float4 v = make_float4(0.f, 0.f, 0.f, 0.f);
            if (gr < n_nodes) v = ((const float4*)x)[(size_t)gr * 32 + c4];
            __half* dst = As + (size_t)r * PADK + c4 * 4;
            dst[0] = __float2half(v.x); dst[1] = __float2half(v.y);
            dst[2] = __float2half(v.z); dst[3] = __float2half(v.w);
        }
        __syncthreads();

        float acc[2][8][4];
        #pragma unroll
        for (int mi = 0; mi < 2; mi++)
            #pragma unroll
            for (int n8 = 0; n8 < 8; n8++)
                acc[mi][n8][0] = acc[mi][n8][1] = acc[mi][n8][2] = acc[mi][n8][3] = 0.f;

        warp_mma_32x64(As + (size_t)(wm * 32) * PADK,
                       Ws + (size_t)(wn * 64) * PADK, acc, lane);

        __half* Yb = g_Y + (half_sel << 7);
        #pragma unroll
        for (int mi = 0; mi < 2; mi++) {
            const int r0 = row0 + wm * 32 + mi * 16 + g;
            #pragma unroll
            for (int n8 = 0; n8 < 8; n8++) {
                int col = wn * 64 + n8 * 8 + 2 * t;
                if (r0 < n_nodes)
                    *(__half2*)(Yb + (size_t)r0 * 256 + col) =
                        __floats2half2_rn(acc[mi][n8][0], acc[mi][n8][1]);
                if (r0 + 8 < n_nodes)
                    *(__half2*)(Yb + (size_t)(r0 + 8) * 256 + col) =
                        __floats2half2_rn(acc[mi][n8][2], acc[mi][n8][3]);
            }
        }
    }
}

// ---------------------------------------------------------------------------
// Edge kernel (persistent, block 256, 2 CTAs/SM) — R10 base + micros:
//  * b2 pre-seeded into acc (no epilogue FADDs)
//  * streaming STG.128 (evict-first: protects g_Y residency in L2)
// ---------------------------------------------------------------------------
__global__ __launch_bounds__(256, 2)
void edge_kernel(const void* __restrict__ edge_index,
                 const float* __restrict__ b1,
                 const float* __restrict__ W2,
                 const float* __restrict__ b2,
                 float* __restrict__ out,
                 int n_edges) {
    extern __shared__ __half smem[];
    __half* Hs0 = smem;                   // [128][PADK]
    __half* Hs1 = smem + 128 * PADK;
    __half* Ws  = smem + 2 * 128 * PADK;  // [128 n][PADK k] = W2[k][n]

    const int tid = threadIdx.x;
    const int warp = tid >> 5, lane = tid & 31;
    const int wm = warp & 3, wn = warp >> 2;   // 4M x 2N
    const int g = lane >> 2, t = lane & 3;
    const bool oddt = (t & 1);

    // Stage W2 once (transposed; coalesced on global side)
    for (int i = tid; i < 128 * 128; i += 256) {
        int k = i >> 7, n = i & 127;
        Ws[(size_t)n * PADK + k] = __float2half(W2[i]);  // W2[k*128+n]
    }

    // Per-lane constants
    const float4 b1v = *(const float4*)(b1 + lane * 4);
    const __half2 b1h0 = __floats2half2_rn(b1v.x, b1v.y);
    const __half2 b1h1 = __floats2half2_rn(b1v.z, b1v.w);
    const __half2 hzero = __float2half2_rn(0.f);

    float2 breg[8];
    #pragma unroll
    for (int n8 = 0; n8 < 8; n8++)
        breg[n8] = *(const float2*)(b2 + wn * 64 + n8 * 8 + 2 * t);
    int colq[4];
    #pragma unroll
    for (int q = 0; q < 4; q++)
        colq[q] = wn * 64 + 16 * q + (oddt ? 8 + 2 * (t - 1) : 2 * t);

    const int is64 = g_idx64;
    const long long* idx64 = (const long long*)edge_index;
    const int*       idx32 = (const int*)edge_index;
    const int n_tiles = (n_edges + 127) >> 7;

    auto load_idx = [&](int tl) -> int {
        int myE = (tl << 7) + (warp << 4) + (lane & 15);
        if (myE >= n_edges) myE = n_edges - 1;
        size_t off = (lane < 16) ? (size_t)myE : (size_t)n_edges + (size_t)myE;
        return is64 ? (int)idx64[off] : idx32[off];
    };

    int tile = blockIdx.x;
    if (tile >= n_tiles) return;
    int vidx = load_idx(tile);   // prologue index load (covered by Ws staging)

    int li = 0;
    while (true) {
        __half* Hs = (li & 1) ? Hs1 : Hs0;
        const int e0 = tile << 7;

        // ---- warp-cooperative gather, batch x8, half2 math ----
        {
            __half* Hrow = Hs + (size_t)(warp << 4) * PADK + lane * 4;
            #pragma unroll
            for (int i = 0; i < 16; i += 8) {
                uint2 va[8], vd[8];
                #pragma unroll
                for (int j = 0; j < 8; j++) {
                    int s = __shfl_sync(FULLMASK, vidx, i + j);
                    int d = __shfl_sync(FULLMASK, vidx, 16 + i + j);
                    va[j] = *(const uint2*)(g_Y + (size_t)s * 256 + lane * 4);
                    vd[j] = *(const uint2*)(g_Y + (size_t)d * 256 + 128 + lane * 4);
                }
                #pragma unroll
                for (int j = 0; j < 8; j++) {
                    __half2 s0 = *(const __half2*)&va[j].x;
                    __half2 s1 = *(const __half2*)&va[j].y;
                    __half2 d0 = *(const __half2*)&vd[j].x;
                    __half2 d1 = *(const __half2*)&vd[j].y;
                    __half2 r0 = __hmax2(__hadd2(__hadd2(s0, d0), b1h0), hzero);
                    __half2 r1 = __hmax2(__hadd2(__hadd2(s1, d1), b1h1), hzero);
                    uint2 rv;
                    rv.x = *(const unsigned*)&r0;
                    rv.y = *(const unsigned*)&r1;
                    *(uint2*)(Hrow + (size_t)(i + j) * PADK) = rv;
                }
            }
        }
        __syncthreads();   // H ready; all warps past previous tile's MMA

        // ---- prefetch next tile's indices (latency hidden under MMA) ----
        const int next = tile + gridDim.x;
        const bool more = next < n_tiles;
        int vnext = more ? load_idx(next) : 0;

        // ---- 32x64 warp-tile GEMM; acc pre-seeded with b2 ----
        float acc[2][8][4];
        #pragma unroll
        for (int mi = 0; mi < 2; mi++)
            #pragma unroll
            for (int n8 = 0; n8 < 8; n8++) {
                acc[mi][n8][0] = breg[n8].x; acc[mi][n8][1] = breg[n8].y;
                acc[mi][n8][2] = breg[n8].x; acc[mi][n8][3] = breg[n8].y;
            }

        warp_mma_32x64(Hs + (size_t)(wm * 32) * PADK,
                       Ws + (size_t)(wn * 64) * PADK, acc, lane);

        // ---- epilogue: shfl-merge lane pairs -> float4, streaming STG.128 ----
        #pragma unroll
        for (int mi = 0; mi < 2; mi++) {
            const int r0 = e0 + wm * 32 + mi * 16 + g;
            #pragma unroll
            for (int q = 0; q < 4; q++) {
                const int n8e = 2 * q, n8o = 2 * q + 1;
                float s0 = oddt ? acc[mi][n8e][0] : acc[mi][n8o][0];
                float s1 = oddt ? acc[mi][n8e][1] : acc[mi][n8o][1];
                float s2 = oddt ? acc[mi][n8e][2] : acc[mi][n8o][2];
                float s3 = oddt ? acc[mi][n8e][3] : acc[mi][n8o][3];
                float x0 = __shfl_xor_sync(FULLMASK, s0, 1);
                float x1 = __shfl_xor_sync(FULLMASK, s1, 1);
                float x2 = __shfl_xor_sync(FULLMASK, s2, 1);
                float x3 = __shfl_xor_sync(FULLMASK, s3, 1);
                float4 v0, v1;
                if (!oddt) {
                    v0 = make_float4(acc[mi][n8e][0], acc[mi][n8e][1], x0, x1);
                    v1 = make_float4(acc[mi][n8e][2], acc[mi][n8e][3], x2, x3);
                } else {
                    v0 = make_float4(x0, x1, acc[mi][n8o][0], acc[mi][n8o][1]);
                    v1 = make_float4(x2, x3, acc[mi][n8o][2], acc[mi][n8o][3]);
                }
                if (r0 < n_edges)
                    stg128_cs(out + (size_t)r0 * 128 + colq[q], v0);
                if (r0 + 8 < n_edges)
                    stg128_cs(out + (size_t)(r0 + 8) * 128 + colq[q], v1);
            }
        }

        if (!more) break;
        tile = next; vidx = vnext; li++;
        // no extra sync: ping-pong H; next gather targets the other buffer
    }
}

// ---------------------------------------------------------------------------
extern "C" void kernel_launch(void* const* d_in, const int* in_sizes, int n_in,
                              void* d_out, int out_size) {
    const float* x  = (const float*)d_in[0];
    const void*  ei = d_in[1];
    const float* W1 = (const float*)d_in[2];
    const float* b1 = (const float*)d_in[3];
    const float* W2 = (const float*)d_in[4];
    const float* b2 = (const float*)d_in[5];
    float* out = (float*)d_out;

    const int n_nodes = in_sizes[0] / 128;
    const int n_edges = in_sizes[1] / 2;

    const int smem3 = 3 * 128 * PADK * (int)sizeof(__half);   // 104448
    static bool attr_set = false;
    if (!attr_set) {
        cudaFuncSetAttribute(node_gemm_kernel,
                             cudaFuncAttributeMaxDynamicSharedMemorySize, smem3);
        cudaFuncSetAttribute(edge_kernel,
                             cudaFuncAttributeMaxDynamicSharedMemorySize, smem3);
        attr_set = true;
    }

    const int node_tiles = (n_nodes + 127) / 128;
    int g1x = node_tiles < 148 ? node_tiles : 148;
    dim3 g1(g1x, 2);
    node_gemm_kernel<<<g1, 256, smem3>>>(x, W1, ei, n_nodes);

    const int edge_tiles = (n_edges + 127) / 128;
    int g2 = edge_tiles < 296 ? edge_tiles : 296;
    edge_kernel<<<g2, 256, smem3>>>(ei, b1, W2, b2, out, n_edges);
}

// round 16
// speedup vs baseline: 1.1942x; 1.0294x over previous
#include <cuda_runtime.h>
#include <cuda_fp16.h>
#include <cstdint>

#define PADK 136           // halfs per smem row (128 + 8 pad) -> conflict-free LDSM
#define FULLMASK 0xffffffffu

// Scratch: per-node transformed features, fp16.
// Y[n, 0:128] = x[n] @ W1a (src half),  Y[n,128:256] = x[n] @ W1b (dst half)
__device__ __half g_Y[(size_t)50000 * 256];
__device__ int g_idx64;

// ---------------------------------------------------------------------------
__device__ __forceinline__ unsigned sptr(const void* p) {
    return (unsigned)__cvta_generic_to_shared(p);
}
__device__ __forceinline__ void ldsm4(unsigned a, unsigned& r0, unsigned& r1,
                                      unsigned& r2, unsigned& r3) {
    asm volatile("ldmatrix.sync.aligned.m8n8.x4.shared.b16 {%0,%1,%2,%3}, [%4];\n"
                 : "=r"(r0), "=r"(r1), "=r"(r2), "=r"(r3) : "r"(a));
}
__device__ __forceinline__ void mma16816(float* c, unsigned a0, unsigned a1,
                                         unsigned a2, unsigned a3,
                                         unsigned b0, unsigned b1) {
    asm volatile(
        "mma.sync.aligned.m16n8k16.row.col.f32.f16.f16.f32 "
        "{%0,%1,%2,%3}, {%4,%5,%6,%7}, {%8,%9}, {%0,%1,%2,%3};\n"
        : "+f"(c[0]), "+f"(c[1]), "+f"(c[2]), "+f"(c[3])
        : "r"(a0), "r"(a1), "r"(a2), "r"(a3), "r"(b0), "r"(b1));
}
__device__ __forceinline__ void stg128_cs(float* p, float4 v) {
    asm volatile("st.global.cs.v4.f32 [%0], {%1,%2,%3,%4};\n"
                 :: "l"(p), "f"(v.x), "f"(v.y), "f"(v.z), "f"(v.w) : "memory");
}
__device__ __forceinline__ float4 ldg128_cs(const float* p) {
    float4 v;
    asm volatile("ld.global.cs.v4.f32 {%0,%1,%2,%3}, [%4];\n"
                 : "=f"(v.x), "=f"(v.y), "=f"(v.z), "=f"(v.w) : "l"(p));
    return v;
}

// ---------------------------------------------------------------------------
// Warp-level 32x64x128 GEMM.
// ---------------------------------------------------------------------------
__device__ __forceinline__ void warp_mma_32x64(const __half* Aw, const __half* Bw,
                                               float acc[2][8][4], int lane) {
    unsigned a_addr = sptr(Aw + (size_t)(lane & 15) * PADK + ((lane & 16) ? 8 : 0));
    unsigned b_addr = sptr(Bw + (size_t)((lane & 7) + ((lane & 16) ? 8 : 0)) * PADK
                              + ((lane & 8) ? 8 : 0));
    #pragma unroll
    for (int k0 = 0; k0 < 128; k0 += 16) {
        unsigned a0[4], a1[4];
        ldsm4(a_addr + k0 * 2, a0[0], a0[1], a0[2], a0[3]);
        ldsm4(a_addr + 16 * PADK * 2 + k0 * 2, a1[0], a1[1], a1[2], a1[3]);
        #pragma unroll
        for (int np = 0; np < 4; np++) {
            unsigned b0, b1, b2, b3;
            ldsm4(b_addr + (unsigned)(np * 16 * PADK * 2) + k0 * 2, b0, b1, b2, b3);
            mma16816(acc[0][2 * np],     a0[0], a0[1], a0[2], a0[3], b0, b1);
            mma16816(acc[0][2 * np + 1], a0[0], a0[1], a0[2], a0[3], b2, b3);
            mma16816(acc[1][2 * np],     a1[0], a1[1], a1[2], a1[3], b0, b1);
            mma16816(acc[1][2 * np + 1], a1[0], a1[1], a1[2], a1[3], b2, b3);
        }
    }
}

// ---------------------------------------------------------------------------
// Node kernel (persistent, block 256, 2 CTAs/SM via y-split) — R10 proven,
// x loads streaming (evict-first: keep L2 for Y).
// ---------------------------------------------------------------------------
__global__ __launch_bounds__(256, 2)
void node_gemm_kernel(const float* __restrict__ x,
                      const float* __restrict__ W1,
                      const void* __restrict__ ei,
                      int n_nodes) {
    extern __shared__ __half smem[];
    __half* As0 = smem;                   // [128][PADK]
    __half* As1 = smem + 128 * PADK;
    __half* Ws  = smem + 2 * 128 * PADK;  // [128 cols][PADK k] for this half

    const int tid = threadIdx.x;
    const int half_sel = blockIdx.y;

    if (blockIdx.x == 0 && half_sel == 0 && tid < 32) {
        const unsigned* w = (const unsigned*)ei;
        unsigned v = w[2 * tid + 1] | w[2 * (tid + 32) + 1];
        int any_nz = __any_sync(FULLMASK, v != 0u);
        if (tid == 0) g_idx64 = any_nz ? 0 : 1;
    }

    for (int i = tid; i < 128 * 128; i += 256) {
        int k = i >> 7, n = i & 127;
        Ws[(size_t)n * PADK + k] =
            __float2half(W1[(size_t)(k + (half_sel << 7)) * 128 + n]);
    }

    const int warp = tid >> 5, lane = tid & 31;
    const int wm = warp & 3, wn = warp >> 2;   // 4M x 2N
    const int g = lane >> 2, t = lane & 3;
    const int n_tiles = (n_nodes + 127) >> 7;

    int li = 0;
    for (int tile = blockIdx.x; tile < n_tiles; tile += gridDim.x, li++) {
        __half* As = (li & 1) ? As1 : As0;
        const int row0 = tile << 7;

        for (int i = tid; i < 128 * 32; i += 256) {
            int r = i >> 5, c4 = i & 31;
            int gr = row0 + r;
            float4 v = make_float4(0.f, 0.f, 0.f, 0.f);
            if (gr < n_nodes) v = ldg128_cs(x + (size_t)gr * 128 + c4 * 4);
            __half* dst = As + (size_t)r * PADK + c4 * 4;
            dst[0] = __float2half(v.x); dst[1] = __float2half(v.y);
            dst[2] = __float2half(v.z); dst[3] = __float2half(v.w);
        }
        __syncthreads();

        float acc[2][8][4];
        #pragma unroll
        for (int mi = 0; mi < 2; mi++)
            #pragma unroll
            for (int n8 = 0; n8 < 8; n8++)
                acc[mi][n8][0] = acc[mi][n8][1] = acc[mi][n8][2] = acc[mi][n8][3] = 0.f;

        warp_mma_32x64(As + (size_t)(wm * 32) * PADK,
                       Ws + (size_t)(wn * 64) * PADK, acc, lane);

        __half* Yb = g_Y + (half_sel << 7);
        #pragma unroll
        for (int mi = 0; mi < 2; mi++) {
            const int r0 = row0 + wm * 32 + mi * 16 + g;
            #pragma unroll
            for (int n8 = 0; n8 < 8; n8++) {
                int col = wn * 64 + n8 * 8 + 2 * t;
                if (r0 < n_nodes)
                    *(__half2*)(Yb + (size_t)r0 * 256 + col) =
                        __floats2half2_rn(acc[mi][n8][0], acc[mi][n8][1]);
                if (r0 + 8 < n_nodes)
                    *(__half2*)(Yb + (size_t)(r0 + 8) * 256 + col) =
                        __floats2half2_rn(acc[mi][n8][2], acc[mi][n8][3]);
            }
        }
    }
}

// ---------------------------------------------------------------------------
// Edge kernel (persistent, block 256, 2 CTAs/SM) — R14 base + __ldg gather
// with R14's EXACT address expressions (R15's stride bug fixed).
// ---------------------------------------------------------------------------
__global__ __launch_bounds__(256, 2)
void edge_kernel(const void* __restrict__ edge_index,
                 const float* __restrict__ b1,
                 const float* __restrict__ W2,
                 const float* __restrict__ b2,
                 float* __restrict__ out,
                 int n_edges) {
    extern __shared__ __half smem[];
    __half* Hs0 = smem;                   // [128][PADK]
    __half* Hs1 = smem + 128 * PADK;
    __half* Ws  = smem + 2 * 128 * PADK;  // [128 n][PADK k] = W2[k][n]

    const int tid = threadIdx.x;
    const int warp = tid >> 5, lane = tid & 31;
    const int wm = warp & 3, wn = warp >> 2;   // 4M x 2N
    const int g = lane >> 2, t = lane & 3;
    const bool oddt = (t & 1);

    // Stage W2 once (transposed; coalesced on global side)
    for (int i = tid; i < 128 * 128; i += 256) {
        int k = i >> 7, n = i & 127;
        Ws[(size_t)n * PADK + k] = __float2half(W2[i]);  // W2[k*128+n]
    }

    // Per-lane constants
    const float4 b1v = *(const float4*)(b1 + lane * 4);
    const __half2 b1h0 = __floats2half2_rn(b1v.x, b1v.y);
    const __half2 b1h1 = __floats2half2_rn(b1v.z, b1v.w);
    const __half2 hzero = __float2half2_rn(0.f);

    float2 breg[8];
    #pragma unroll
    for (int n8 = 0; n8 < 8; n8++)
        breg[n8] = *(const float2*)(b2 + wn * 64 + n8 * 8 + 2 * t);
    int colq[4];
    #pragma unroll
    for (int q = 0; q < 4; q++)
        colq[q] = wn * 64 + 16 * q + (oddt ? 8 + 2 * (t - 1) : 2 * t);

    const int is64 = g_idx64;
    const long long* idx64 = (const long long*)edge_index;
    const int*       idx32 = (const int*)edge_index;
    const int n_tiles = (n_edges + 127) >> 7;

    auto load_idx = [&](int tl) -> int {
        int myE = (tl << 7) + (warp << 4) + (lane & 15);
        if (myE >= n_edges) myE = n_edges - 1;
        size_t off = (lane < 16) ? (size_t)myE : (size_t)n_edges + (size_t)myE;
        return is64 ? (int)idx64[off] : idx32[off];
    };

    int tile = blockIdx.x;
    if (tile >= n_tiles) return;
    int vidx = load_idx(tile);   // prologue index load (covered by Ws staging)

    int li = 0;
    while (true) {
        __half* Hs = (li & 1) ? Hs1 : Hs0;
        const int e0 = tile << 7;

        // ---- warp-cooperative gather, batch x8, half2 math, LDG.NC ----
        {
            __half* Hrow = Hs + (size_t)(warp << 4) * PADK + lane * 4;
            #pragma unroll
            for (int i = 0; i < 16; i += 8) {
                uint2 va[8], vd[8];
                #pragma unroll
                for (int j = 0; j < 8; j++) {
                    int s = __shfl_sync(FULLMASK, vidx, i + j);
                    int d = __shfl_sync(FULLMASK, vidx, 16 + i + j);
                    // R14 addresses, wrapped in __ldg (read-only NC path)
                    va[j] = __ldg((const uint2*)(g_Y + (size_t)s * 256 + lane * 4));
                    vd[j] = __ldg((const uint2*)(g_Y + (size_t)d * 256 + 128 + lane * 4));
                }
                #pragma unroll
                for (int j = 0; j < 8; j++) {
                    __half2 s0 = *(const __half2*)&va[j].x;
                    __half2 s1 = *(const __half2*)&va[j].y;
                    __half2 d0 = *(const __half2*)&vd[j].x;
                    __half2 d1 = *(const __half2*)&vd[j].y;
                    __half2 r0 = __hmax2(__hadd2(__hadd2(s0, d0), b1h0), hzero);
                    __half2 r1 = __hmax2(__hadd2(__hadd2(s1, d1), b1h1), hzero);
                    uint2 rv;
                    rv.x = *(const unsigned*)&r0;
                    rv.y = *(const unsigned*)&r1;
                    *(uint2*)(Hrow + (size_t)(i + j) * PADK) = rv;
                }
            }
        }
        __syncthreads();   // H ready; all warps past previous tile's MMA

        // ---- prefetch next tile's indices (latency hidden under MMA) ----
        const int next = tile + gridDim.x;
        const bool more = next < n_tiles;
        int vnext = more ? load_idx(next) : 0;

        // ---- 32x64 warp-tile GEMM; acc pre-seeded with b2 ----
        float acc[2][8][4];
        #pragma unroll
        for (int mi = 0; mi < 2; mi++)
            #pragma unroll
            for (int n8 = 0; n8 < 8; n8++) {
                acc[mi][n8][0] = breg[n8].x; acc[mi][n8][1] = breg[n8].y;
                acc[mi][n8][2] = breg[n8].x; acc[mi][n8][3] = breg[n8].y;
            }

        warp_mma_32x64(Hs + (size_t)(wm * 32) * PADK,
                       Ws + (size_t)(wn * 64) * PADK, acc, lane);

        // ---- epilogue: shfl-merge lane pairs -> float4, streaming STG.128 ----
        #pragma unroll
        for (int mi = 0; mi < 2; mi++) {
            const int r0 = e0 + wm * 32 + mi * 16 + g;
            #pragma unroll
            for (int q = 0; q < 4; q++) {
                const int n8e = 2 * q, n8o = 2 * q + 1;
                float s0 = oddt ? acc[mi][n8e][0] : acc[mi][n8o][0];
                float s1 = oddt ? acc[mi][n8e][1] : acc[mi][n8o][1];
                float s2 = oddt ? acc[mi][n8e][2] : acc[mi][n8o][2];
                float s3 = oddt ? acc[mi][n8e][3] : acc[mi][n8o][3];
                float x0 = __shfl_xor_sync(FULLMASK, s0, 1);
                float x1 = __shfl_xor_sync(FULLMASK, s1, 1);
                float x2 = __shfl_xor_sync(FULLMASK, s2, 1);
                float x3 = __shfl_xor_sync(FULLMASK, s3, 1);
                float4 v0, v1;
                if (!oddt) {
                    v0 = make_float4(acc[mi][n8e][0], acc[mi][n8e][1], x0, x1);
                    v1 = make_float4(acc[mi][n8e][2], acc[mi][n8e][3], x2, x3);
                } else {
                    v0 = make_float4(x0, x1, acc[mi][n8o][0], acc[mi][n8o][1]);
                    v1 = make_float4(x2, x3, acc[mi][n8o][2], acc[mi][n8o][3]);
                }
                if (r0 < n_edges)
                    stg128_cs(out + (size_t)r0 * 128 + colq[q], v0);
                if (r0 + 8 < n_edges)
                    stg128_cs(out + (size_t)(r0 + 8) * 128 + colq[q], v1);
            }
        }

        if (!more) break;
        tile = next; vidx = vnext; li++;
        // no extra sync: ping-pong H; next gather targets the other buffer
    }
}

// ---------------------------------------------------------------------------
extern "C" void kernel_launch(void* const* d_in, const int* in_sizes, int n_in,
                              void* d_out, int out_size) {
    const float* x  = (const float*)d_in[0];
    const void*  ei = d_in[1];
    const float* W1 = (const float*)d_in[2];
    const float* b1 = (const float*)d_in[3];
    const float* W2 = (const float*)d_in[4];
    const float* b2 = (const float*)d_in[5];
    float* out = (float*)d_out;

    const int n_nodes = in_sizes[0] / 128;
    const int n_edges = in_sizes[1] / 2;

    const int smem3 = 3 * 128 * PADK * (int)sizeof(__half);   // 104448
    static bool attr_set = false;
    if (!attr_set) {
        cudaFuncSetAttribute(node_gemm_kernel,
                             cudaFuncAttributeMaxDynamicSharedMemorySize, smem3);
        cudaFuncSetAttribute(edge_kernel,
                             cudaFuncAttributeMaxDynamicSharedMemorySize, smem3);
        attr_set = true;
    }

    const int node_tiles = (n_nodes + 127) / 128;
    int g1x = node_tiles < 148 ? node_tiles : 148;
    dim3 g1(g1x, 2);
    node_gemm_kernel<<<g1, 256, smem3>>>(x, W1, ei, n_nodes);

    const int edge_tiles = (n_edges + 127) / 128;
    int g2 = edge_tiles < 296 ? edge_tiles : 296;
    edge_kernel<<<g2, 256, smem3>>>(ei, b1, W2, b2, out, n_edges);
}

// round 17
// speedup vs baseline: 1.1957x; 1.0012x over previous
#include <cuda_runtime.h>
#include <cuda_fp16.h>
#include <cstdint>

#define PADK 136           // halfs per smem row (128 + 8 pad) -> conflict-free LDSM
#define FULLMASK 0xffffffffu

// Scratch: per-node transformed features, fp16 (b1/2 pre-folded into each half).
// Y[n, 0:128] = x[n] @ W1a + b1/2,  Y[n,128:256] = x[n] @ W1b + b1/2
__device__ __half g_Y[(size_t)50000 * 256];
__device__ int g_idx64;

// ---------------------------------------------------------------------------
__device__ __forceinline__ unsigned sptr(const void* p) {
    return (unsigned)__cvta_generic_to_shared(p);
}
__device__ __forceinline__ void ldsm4(unsigned a, unsigned& r0, unsigned& r1,
                                      unsigned& r2, unsigned& r3) {
    asm volatile("ldmatrix.sync.aligned.m8n8.x4.shared.b16 {%0,%1,%2,%3}, [%4];\n"
                 : "=r"(r0), "=r"(r1), "=r"(r2), "=r"(r3) : "r"(a));
}
__device__ __forceinline__ void mma16816(float* c, unsigned a0, unsigned a1,
                                         unsigned a2, unsigned a3,
                                         unsigned b0, unsigned b1) {
    asm volatile(
        "mma.sync.aligned.m16n8k16.row.col.f32.f16.f16.f32 "
        "{%0,%1,%2,%3}, {%4,%5,%6,%7}, {%8,%9}, {%0,%1,%2,%3};\n"
        : "+f"(c[0]), "+f"(c[1]), "+f"(c[2]), "+f"(c[3])
        : "r"(a0), "r"(a1), "r"(a2), "r"(a3), "r"(b0), "r"(b1));
}
__device__ __forceinline__ void stg128_cs(float* p, float4 v) {
    asm volatile("st.global.cs.v4.f32 [%0], {%1,%2,%3,%4};\n"
                 :: "l"(p), "f"(v.x), "f"(v.y), "f"(v.z), "f"(v.w) : "memory");
}
__device__ __forceinline__ float4 ldg128_cs(const float* p) {
    float4 v;
    asm volatile("ld.global.cs.v4.f32 {%0,%1,%2,%3}, [%4];\n"
                 : "=f"(v.x), "=f"(v.y), "=f"(v.z), "=f"(v.w) : "l"(p));
    return v;
}

// ---------------------------------------------------------------------------
// Warp-level 32x64x128 GEMM.
// ---------------------------------------------------------------------------
__device__ __forceinline__ void warp_mma_32x64(const __half* Aw, const __half* Bw,
                                               float acc[2][8][4], int lane) {
    unsigned a_addr = sptr(Aw + (size_t)(lane & 15) * PADK + ((lane & 16) ? 8 : 0));
    unsigned b_addr = sptr(Bw + (size_t)((lane & 7) + ((lane & 16) ? 8 : 0)) * PADK
                              + ((lane & 8) ? 8 : 0));
    #pragma unroll
    for (int k0 = 0; k0 < 128; k0 += 16) {
        unsigned a0[4], a1[4];
        ldsm4(a_addr + k0 * 2, a0[0], a0[1], a0[2], a0[3]);
        ldsm4(a_addr + 16 * PADK * 2 + k0 * 2, a1[0], a1[1], a1[2], a1[3]);
        #pragma unroll
        for (int np = 0; np < 4; np++) {
            unsigned b0, b1, b2, b3;
            ldsm4(b_addr + (unsigned)(np * 16 * PADK * 2) + k0 * 2, b0, b1, b2, b3);
            mma16816(acc[0][2 * np],     a0[0], a0[1], a0[2], a0[3], b0, b1);
            mma16816(acc[0][2 * np + 1], a0[0], a0[1], a0[2], a0[3], b2, b3);
            mma16816(acc[1][2 * np],     a1[0], a1[1], a1[2], a1[3], b0, b1);
            mma16816(acc[1][2 * np + 1], a1[0], a1[1], a1[2], a1[3], b2, b3);
        }
    }
}

// ---------------------------------------------------------------------------
// Node kernel (persistent, block 256, 2 CTAs/SM via y-split):
//   Y-half = x @ W1-half + b1/2   (b1 pre-split so edge gather skips the add)
// x loads streaming (evict-first: keep L2 for Y).
// ---------------------------------------------------------------------------
__global__ __launch_bounds__(256, 2)
void node_gemm_kernel(const float* __restrict__ x,
                      const float* __restrict__ W1,
                      const float* __restrict__ b1,
                      const void* __restrict__ ei,
                      int n_nodes) {
    extern __shared__ __half smem[];
    __half* As0 = smem;                   // [128][PADK]
    __half* As1 = smem + 128 * PADK;
    __half* Ws  = smem + 2 * 128 * PADK;  // [128 cols][PADK k] for this half

    const int tid = threadIdx.x;
    const int half_sel = blockIdx.y;

    if (blockIdx.x == 0 && half_sel == 0 && tid < 32) {
        const unsigned* w = (const unsigned*)ei;
        unsigned v = w[2 * tid + 1] | w[2 * (tid + 32) + 1];
        int any_nz = __any_sync(FULLMASK, v != 0u);
        if (tid == 0) g_idx64 = any_nz ? 0 : 1;
    }

    for (int i = tid; i < 128 * 128; i += 256) {
        int k = i >> 7, n = i & 127;
        Ws[(size_t)n * PADK + k] =
            __float2half(W1[(size_t)(k + (half_sel << 7)) * 128 + n]);
    }

    const int warp = tid >> 5, lane = tid & 31;
    const int wm = warp & 3, wn = warp >> 2;   // 4M x 2N
    const int g = lane >> 2, t = lane & 3;
    const int n_tiles = (n_nodes + 127) >> 7;

    // acc seed: 0.5*b1 at this lane's output columns (same for both halves)
    float2 bseed[8];
    #pragma unroll
    for (int n8 = 0; n8 < 8; n8++) {
        float2 b = *(const float2*)(b1 + wn * 64 + n8 * 8 + 2 * t);
        bseed[n8] = make_float2(0.5f * b.x, 0.5f * b.y);
    }

    int li = 0;
    for (int tile = blockIdx.x; tile < n_tiles; tile += gridDim.x, li++) {
        __half* As = (li & 1) ? As1 : As0;
        const int row0 = tile << 7;

        for (int i = tid; i < 128 * 32; i += 256) {
            int r = i >> 5, c4 = i & 31;
            int gr = row0 + r;
            float4 v = make_float4(0.f, 0.f, 0.f, 0.f);
            if (gr < n_nodes) v = ldg128_cs(x + (size_t)gr * 128 + c4 * 4);
            __half* dst = As + (size_t)r * PADK + c4 * 4;
            dst[0] = __float2half(v.x); dst[1] = __float2half(v.y);
            dst[2] = __float2half(v.z); dst[3] = __float2half(v.w);
        }
        __syncthreads();

        float acc[2][8][4];
        #pragma unroll
        for (int mi = 0; mi < 2; mi++)
            #pragma unroll
            for (int n8 = 0; n8 < 8; n8++) {
                acc[mi][n8][0] = bseed[n8].x; acc[mi][n8][1] = bseed[n8].y;
                acc[mi][n8][2] = bseed[n8].x; acc[mi][n8][3] = bseed[n8].y;
            }

        warp_mma_32x64(As + (size_t)(wm * 32) * PADK,
                       Ws + (size_t)(wn * 64) * PADK, acc, lane);

        __half* Yb = g_Y + (half_sel << 7);
        #pragma unroll
        for (int mi = 0; mi < 2; mi++) {
            const int r0 = row0 + wm * 32 + mi * 16 + g;
            #pragma unroll
            for (int n8 = 0; n8 < 8; n8++) {
                int col = wn * 64 + n8 * 8 + 2 * t;
                if (r0 < n_nodes)
                    *(__half2*)(Yb + (size_t)r0 * 256 + col) =
                        __floats2half2_rn(acc[mi][n8][0], acc[mi][n8][1]);
                if (r0 + 8 < n_nodes)
                    *(__half2*)(Yb + (size_t)(r0 + 8) * 256 + col) =
                        __floats2half2_rn(acc[mi][n8][2], acc[mi][n8][3]);
            }
        }
    }
}

// ---------------------------------------------------------------------------
// Edge kernel (persistent, block 256, 2 CTAs/SM) — R14 gather form (plain
// loads; __ldg reverted), b1 already folded into Y: h = relu(s + d).
// ---------------------------------------------------------------------------
__global__ __launch_bounds__(256, 2)
void edge_kernel(const void* __restrict__ edge_index,
                 const float* __restrict__ W2,
                 const float* __restrict__ b2,
                 float* __restrict__ out,
                 int n_edges) {
    extern __shared__ __half smem[];
    __half* Hs0 = smem;                   // [128][PADK]
    __half* Hs1 = smem + 128 * PADK;
    __half* Ws  = smem + 2 * 128 * PADK;  // [128 n][PADK k] = W2[k][n]

    const int tid = threadIdx.x;
    const int warp = tid >> 5, lane = tid & 31;
    const int wm = warp & 3, wn = warp >> 2;   // 4M x 2N
    const int g = lane >> 2, t = lane & 3;
    const bool oddt = (t & 1);

    // Stage W2 once (transposed; coalesced on global side)
    for (int i = tid; i < 128 * 128; i += 256) {
        int k = i >> 7, n = i & 127;
        Ws[(size_t)n * PADK + k] = __float2half(W2[i]);  // W2[k*128+n]
    }

    const __half2 hzero = __float2half2_rn(0.f);

    float2 breg[8];
    #pragma unroll
    for (int n8 = 0; n8 < 8; n8++)
        breg[n8] = *(const float2*)(b2 + wn * 64 + n8 * 8 + 2 * t);
    int colq[4];
    #pragma unroll
    for (int q = 0; q < 4; q++)
        colq[q] = wn * 64 + 16 * q + (oddt ? 8 + 2 * (t - 1) : 2 * t);

    const int is64 = g_idx64;
    const long long* idx64 = (const long long*)edge_index;
    const int*       idx32 = (const int*)edge_index;
    const int n_tiles = (n_edges + 127) >> 7;

    auto load_idx = [&](int tl) -> int {
        int myE = (tl << 7) + (warp << 4) + (lane & 15);
        if (myE >= n_edges) myE = n_edges - 1;
        size_t off = (lane < 16) ? (size_t)myE : (size_t)n_edges + (size_t)myE;
        return is64 ? (int)idx64[off] : idx32[off];
    };

    int tile = blockIdx.x;
    if (tile >= n_tiles) return;
    int vidx = load_idx(tile);   // prologue index load (covered by Ws staging)

    int li = 0;
    while (true) {
        __half* Hs = (li & 1) ? Hs1 : Hs0;
        const int e0 = tile << 7;

        // ---- warp-cooperative gather, batch x8: h = relu(s + d) ----
        {
            __half* Hrow = Hs + (size_t)(warp << 4) * PADK + lane * 4;
            #pragma unroll
            for (int i = 0; i < 16; i += 8) {
                uint2 va[8], vd[8];
                #pragma unroll
                for (int j = 0; j < 8; j++) {
                    int s = __shfl_sync(FULLMASK, vidx, i + j);
                    int d = __shfl_sync(FULLMASK, vidx, 16 + i + j);
                    va[j] = *(const uint2*)(g_Y + (size_t)s * 256 + lane * 4);
                    vd[j] = *(const uint2*)(g_Y + (size_t)d * 256 + 128 + lane * 4);
                }
                #pragma unroll
                for (int j = 0; j < 8; j++) {
                    __half2 s0 = *(const __half2*)&va[j].x;
                    __half2 s1 = *(const __half2*)&va[j].y;
                    __half2 d0 = *(const __half2*)&vd[j].x;
                    __half2 d1 = *(const __half2*)&vd[j].y;
                    __half2 r0 = __hmax2(__hadd2(s0, d0), hzero);
                    __half2 r1 = __hmax2(__hadd2(s1, d1), hzero);
                    uint2 rv;
                    rv.x = *(const unsigned*)&r0;
                    rv.y = *(const unsigned*)&r1;
                    *(uint2*)(Hrow + (size_t)(i + j) * PADK) = rv;
                }
            }
        }
        __syncthreads();   // H ready; all warps past previous tile's MMA

        // ---- prefetch next tile's indices (latency hidden under MMA) ----
        const int next = tile + gridDim.x;
        const bool more = next < n_tiles;
        int vnext = more ? load_idx(next) : 0;

        // ---- 32x64 warp-tile GEMM; acc pre-seeded with b2 ----
        float acc[2][8][4];
        #pragma unroll
        for (int mi = 0; mi < 2; mi++)
            #pragma unroll
            for (int n8 = 0; n8 < 8; n8++) {
                acc[mi][n8][0] = breg[n8].x; acc[mi][n8][1] = breg[n8].y;
                acc[mi][n8][2] = breg[n8].x; acc[mi][n8][3] = breg[n8].y;
            }

        warp_mma_32x64(Hs + (size_t)(wm * 32) * PADK,
                       Ws + (size_t)(wn * 64) * PADK, acc, lane);

        // ---- epilogue: shfl-merge lane pairs -> float4, streaming STG.128 ----
        #pragma unroll
        for (int mi = 0; mi < 2; mi++) {
            const int r0 = e0 + wm * 32 + mi * 16 + g;
            #pragma unroll
            for (int q = 0; q < 4; q++) {
                const int n8e = 2 * q, n8o = 2 * q + 1;
                float s0 = oddt ? acc[mi][n8e][0] : acc[mi][n8o][0];
                float s1 = oddt ? acc[mi][n8e][1] : acc[mi][n8o][1];
                float s2 = oddt ? acc[mi][n8e][2] : acc[mi][n8o][2];
                float s3 = oddt ? acc[mi][n8e][3] : acc[mi][n8o][3];
                float x0 = __shfl_xor_sync(FULLMASK, s0, 1);
                float x1 = __shfl_xor_sync(FULLMASK, s1, 1);
                float x2 = __shfl_xor_sync(FULLMASK, s2, 1);
                float x3 = __shfl_xor_sync(FULLMASK, s3, 1);
                float4 v0, v1;
                if (!oddt) {
                    v0 = make_float4(acc[mi][n8e][0], acc[mi][n8e][1], x0, x1);
                    v1 = make_float4(acc[mi][n8e][2], acc[mi][n8e][3], x2, x3);
                } else {
                    v0 = make_float4(x0, x1, acc[mi][n8o][0], acc[mi][n8o][1]);
                    v1 = make_float4(x2, x3, acc[mi][n8o][2], acc[mi][n8o][3]);
                }
                if (r0 < n_edges)
                    stg128_cs(out + (size_t)r0 * 128 + colq[q], v0);
                if (r0 + 8 < n_edges)
                    stg128_cs(out + (size_t)(r0 + 8) * 128 + colq[q], v1);
            }
        }

        if (!more) break;
        tile = next; vidx = vnext; li++;
        // no extra sync: ping-pong H; next gather targets the other buffer
    }
}

// ---------------------------------------------------------------------------
extern "C" void kernel_launch(void* const* d_in, const int* in_sizes, int n_in,
                              void* d_out, int out_size) {
    const float* x  = (const float*)d_in[0];
    const void*  ei = d_in[1];
    const float* W1 = (const float*)d_in[2];
    const float* b1 = (const float*)d_in[3];
    const float* W2 = (const float*)d_in[4];
    const float* b2 = (const float*)d_in[5];
    float* out = (float*)d_out;

    const int n_nodes = in_sizes[0] / 128;
    const int n_edges = in_sizes[1] / 2;

    const int smem3 = 3 * 128 * PADK * (int)sizeof(__half);   // 104448
    static bool attr_set = false;
    if (!attr_set) {
        cudaFuncSetAttribute(node_gemm_kernel,
                             cudaFuncAttributeMaxDynamicSharedMemorySize, smem3);
        cudaFuncSetAttribute(edge_kernel,
                             cudaFuncAttributeMaxDynamicSharedMemorySize, smem3);
        attr_set = true;
    }

    const int node_tiles = (n_nodes + 127) / 128;
    int g1x = node_tiles < 148 ? node_tiles : 148;
    dim3 g1(g1x, 2);
    node_gemm_kernel<<<g1, 256, smem3>>>(x, W1, b1, ei, n_nodes);

    const int edge_tiles = (n_edges + 127) / 128;
    int g2 = edge_tiles < 296 ? edge_tiles : 296;
    edge_kernel<<<g2, 256, smem3>>>(ei, W2, b2, out, n_edges);
}